// round 12
// baseline (speedup 1.0000x reference)
#include <cuda_runtime.h>
#include <math.h>

#define B_    256
#define N_    1152
#define C_    10
#define IN_   8
#define KO_   160
#define NG_   8                    // n per CTA
#define GRID_ 144                  // N_/NG_
#define NT_   1024                 // threads per gemm CTA

typedef unsigned long long u64;

#define WS2_ELEMS (NG_ * KO_ * IN_)          // 10240 u64 = 80 KB
#define DYN_BYTES (WS2_ELEMS * 8)

// partials layout [ko][slab][b]
__device__ float g_p[(size_t)KO_ * GRID_ * B_];
__device__ float g_xT[(size_t)N_ * IN_ * B_];
__device__ float g_vT[KO_ * B_];
__device__ float g_bij[N_ * C_];

// ---- packed f32x2 helpers --------------------------------------------------
__device__ __forceinline__ u64 pk(float lo, float hi) {
    u64 d; asm("mov.b64 %0, {%1, %2};" : "=l"(d) : "f"(lo), "f"(hi)); return d;
}
__device__ __forceinline__ void upk(u64 d, float& lo, float& hi) {
    asm("mov.b64 {%0, %1}, %2;" : "=f"(lo), "=f"(hi) : "l"(d));
}
__device__ __forceinline__ u64 fma2(u64 a, u64 b, u64 c) {
    u64 d; asm("fma.rn.f32x2 %0, %1, %2, %3;" : "=l"(d) : "l"(a), "l"(b), "l"(c));
    return d;
}

__global__ void noop_k() {}
__global__ void zero_bij() { g_bij[blockIdx.x * 256 + threadIdx.x] = 0.f; }

// ---------------------------------------------------------------------------
// K0: transpose x[b][(n,i)] -> xT[(n,i)][b].
// ---------------------------------------------------------------------------
__global__ __launch_bounds__(256) void xpose(const float* __restrict__ x)
{
    __shared__ float tile[32][33];
    const int cb = blockIdx.x * 32, bb = blockIdx.y * 32;
    const int tx = threadIdx.x, ty = threadIdx.y;
#pragma unroll
    for (int k = 0; k < 4; k++)
        tile[ty + 8 * k][tx] = x[(size_t)(bb + ty + 8 * k) * (N_ * IN_) + cb + tx];
    __syncthreads();
#pragma unroll
    for (int k = 0; k < 4; k++)
        g_xT[(size_t)(cb + ty + 8 * k) * B_ + bb + tx] = tile[tx][ty + 8 * k];
}

extern __shared__ u64 dynsm[];   // packed W: 80 KB

// ---------------------------------------------------------------------------
// s-mainloop: thread owns b-pair bp (b=2bp,2bp+1) and kg; ko = kg + 8*jj.
// ko processed in 4 quarters of 5 jj (sp[5] -> 10 regs).
// ---------------------------------------------------------------------------
__device__ __forceinline__ void s_mainloop(const u64* Wc2, int n0, int slab,
                                           int bp, int kg)
{
    for (int koq = 0; koq < 4; koq++) {
        u64 sp[5];
#pragma unroll
        for (int j = 0; j < 5; j++) sp[j] = 0ull;

        for (int nn = 0; nn < NG_; nn++) {
            const int n = n0 + nn;
            u64 xp[IN_];
#pragma unroll
            for (int i = 0; i < IN_; i++) {
                float2 xv = __ldg((const float2*)(g_xT + ((size_t)n * IN_ + i) * B_) + bp);
                xp[i] = pk(xv.x, xv.y);
            }
            const u64* wn = Wc2 + nn * (KO_ * IN_) + kg * IN_;
#pragma unroll
            for (int j = 0; j < 5; j++) {
                const u64* wj = wn + 64 * (koq * 5 + j);
                u64 acc = sp[j];
#pragma unroll
                for (int i = 0; i < IN_; i++)
                    acc = fma2(wj[i], xp[i], acc);
                sp[j] = acc;
            }
        }
#pragma unroll
        for (int j = 0; j < 5; j++) {
            const int ko = kg + 8 * (koq * 5 + j);
            ((u64*)(g_p + ((size_t)ko * GRID_ + slab) * B_))[bp] = sp[j];
        }
    }
}

// ---------------------------------------------------------------------------
// S0: uniform c = 1/C folded into W at staging. 1024 threads.
// ---------------------------------------------------------------------------
__global__ __launch_bounds__(NT_, 1) void s_fold(const float* __restrict__ W)
{
    u64* Wc2 = dynsm;
    const int t = threadIdx.x, bp = t & 127, kg = t >> 7;
    const int n0 = blockIdx.x * NG_;

    for (int j = t; j < WS2_ELEMS; j += NT_) {
        float w = __ldg(&W[(size_t)(n0 + j / 1280) * 1280 + (j % 1280)]) * 0.1f;
        Wc2[j] = pk(w, w);
    }
    __syncthreads();
    s_mainloop(Wc2, n0, blockIdx.x, bp, kg);
}

// ---------------------------------------------------------------------------
// AS-fused: a-dots (u on the fly, scalar fp32 accumulators) -> batched
// softmax -> in-place rescale W by c -> s-mainloop. 1024 threads.
// ---------------------------------------------------------------------------
__global__ __launch_bounds__(NT_, 1) void as_fused(const float* __restrict__ W)
{
    u64* Ws2 = dynsm;
    __shared__ float wredN[NG_][32][C_];   // 10.2 KB
    __shared__ float cs[NG_][C_];
    const int t = threadIdx.x, bp = t & 127, kg = t >> 7;
    const int wid = t >> 5, lane = t & 31;
    const int n0 = blockIdx.x * NG_;

    for (int j = t; j < WS2_ELEMS; j += NT_) {
        float w = __ldg(&W[(size_t)(n0 + j / 1280) * 1280 + (j % 1280)]);
        Ws2[j] = pk(w, w);
    }
    __syncthreads();

    // ---- a-phase ----
    for (int nn = 0; nn < NG_; nn++) {
        const int n = n0 + nn;
        u64 xp[IN_];
#pragma unroll
        for (int i = 0; i < IN_; i++) {
            float2 xv = __ldg((const float2*)(g_xT + ((size_t)n * IN_ + i) * B_) + bp);
            xp[i] = pk(xv.x, xv.y);
        }
        const u64* wn = Ws2 + nn * (KO_ * IN_) + kg * IN_;

        float acc[C_];
#pragma unroll
        for (int k = 0; k < C_; k++) acc[k] = 0.f;
#pragma unroll
        for (int jj = 0; jj < 20; jj++) {
            const u64* wj = wn + 64 * jj;              // ko = kg + 8*jj
            u64 u = 0ull;
#pragma unroll
            for (int i = 0; i < IN_; i++)
                u = fma2(wj[i], xp[i], u);
            const int ko = kg + 8 * jj;
            float2 v = __ldg((const float2*)(g_vT + (size_t)ko * B_) + bp);
            float ulo, uhi; upk(u, ulo, uhi);
            acc[jj >> 1] = fmaf(ulo, v.x, fmaf(uhi, v.y, acc[jj >> 1]));
        }
#pragma unroll
        for (int k = 0; k < C_; k++) {
            float a = acc[k];
#pragma unroll
            for (int m = 16; m >= 1; m >>= 1)
                a += __shfl_xor_sync(0xffffffffu, a, m);
            if (lane == 0) wredN[nn][wid][k] = a;
        }
    }
    __syncthreads();

    // ---- batched softmax: warp wid (<8) handles n0+wid ----
    if (wid < NG_ && lane < 16) {
        const int n = n0 + wid;
        float bn = -1e30f;
        if (lane < C_) {
            float a = 0.f;
#pragma unroll
            for (int w = 0; w < 32; w++) a += wredN[wid][w][lane];
            bn = a * (1.0f / (float)B_) + g_bij[n * C_ + lane];
            g_bij[n * C_ + lane] = bn;
        }
        float mx = bn;
#pragma unroll
        for (int m = 8; m >= 1; m >>= 1)
            mx = fmaxf(mx, __shfl_xor_sync(0x0000ffffu, mx, m, 16));
        float e = (lane < C_) ? expf(bn - mx) : 0.f;
        float sm = e;
#pragma unroll
        for (int m = 8; m >= 1; m >>= 1)
            sm += __shfl_xor_sync(0x0000ffffu, sm, m, 16);
        if (lane < C_) cs[wid][lane] = e / sm;
    }
    __syncthreads();

    // ---- rescale W in place: Wc = c[n,k] * W ----
    for (int j = t; j < WS2_ELEMS; j += NT_) {
        const int nl = j / 1280, rem = j - nl * 1280;
        const int k = rem >> 7;
        float lo, hi; upk(Ws2[j], lo, hi);
        float w = lo * cs[nl][k];
        Ws2[j] = pk(w, w);
    }
    __syncthreads();

    // ---- s-phase ----
    s_mainloop(Ws2, n0, blockIdx.x, bp, kg);
}

// ---------------------------------------------------------------------------
// Reduce 144 slabs ([ko][slab][b]: 1KB strides) + squash. (verified R11)
// ---------------------------------------------------------------------------
__global__ __launch_bounds__(256) void reduce_sq(int final_out, float* __restrict__ out)
{
    __shared__ float4 red[16][16];
    const int ko = blockIdx.x, q = blockIdx.y, t = threadIdx.x;
    const int quad = t & 15, sg = t >> 4;

    const float4* pp = (const float4*)(g_p + (size_t)ko * GRID_ * B_) + q * 16 + quad;
    const size_t str = B_ / 4;

    float4 s = make_float4(0.f, 0.f, 0.f, 0.f);
#pragma unroll
    for (int j = 0; j < 9; j++) {
        float4 p = pp[(size_t)(sg * 9 + j) * str];
        s.x += p.x; s.y += p.y; s.z += p.z; s.w += p.w;
    }
    red[sg][quad] = s;
    __syncthreads();

    if (t < 16) {
        float4 a = red[0][t];
#pragma unroll
        for (int g = 1; g < 16; g++) {
            float4 p = red[g][t];
            a.x += p.x; a.y += p.y; a.z += p.z; a.w += p.w;
        }
        float4 v;
        v.x = a.x * fabsf(a.x) / (1.0f + a.x * a.x);
        v.y = a.y * fabsf(a.y) / (1.0f + a.y * a.y);
        v.z = a.z * fabsf(a.z) / (1.0f + a.z * a.z);
        v.w = a.w * fabsf(a.w) / (1.0f + a.w * a.w);
        if (final_out) {
            const int b0 = q * 64 + t * 4;
            out[(b0 + 0) * KO_ + ko] = v.x;
            out[(b0 + 1) * KO_ + ko] = v.y;
            out[(b0 + 2) * KO_ + ko] = v.z;
            out[(b0 + 3) * KO_ + ko] = v.w;
        } else {
            ((float4*)g_vT)[ko * 64 + q * 16 + t] = v;
        }
    }
}

// ---------------------------------------------------------------------------
extern "C" void kernel_launch(void* const* d_in, const int* in_sizes, int n_in,
                              void* d_out, int out_size)
{
    const float* x = (const float*)d_in[0];
    const float* W = (const float*)d_in[1];
    if (in_sizes[0] == N_ * C_ * 16 * IN_) { const float* t = x; x = W; W = t; }
    float* out = (float*)d_out;

    cudaFuncSetAttribute(s_fold,   cudaFuncAttributeMaxDynamicSharedMemorySize, DYN_BYTES);
    cudaFuncSetAttribute(as_fused, cudaFuncAttributeMaxDynamicSharedMemorySize, DYN_BYTES);

    zero_bij<<<45, 256>>>();                                  // #0
    xpose<<<dim3(N_ * IN_ / 32, B_ / 32), dim3(32, 8)>>>(x);  // #1
    noop_k<<<1, 32>>>();                                      // #2 (capture pad)
    s_fold<<<GRID_, NT_, DYN_BYTES>>>(W);                     // #3  <- ncu slot
    reduce_sq<<<dim3(KO_, 4), 256>>>(0, nullptr);             // #4  v0
    as_fused<<<GRID_, NT_, DYN_BYTES>>>(W);                   // #5  a0+s1
    reduce_sq<<<dim3(KO_, 4), 256>>>(0, nullptr);             // #6  v1
    as_fused<<<GRID_, NT_, DYN_BYTES>>>(W);                   // #7  a1+s2
    reduce_sq<<<dim3(KO_, 4), 256>>>(1, out);                 // #8  v2 -> d_out
}